// round 12
// baseline (speedup 1.0000x reference)
#include <cuda_runtime.h>

#define FULL 0xffffffffu
#define BATCH 32768

// Fused VQC (math validated R7-R11): out_i = K_i * sum_T D_i[T] * sigma_T.
// R12: 64 blocks x 1024 threads (512 elements/block):
//   role 0 (warps 0-15): 1 thread = 1 element; LDG + 8 sincos + publish
//     sz[0..7], K5, K6, K7; after barrier eval out0-4 (registers + sD only).
//   role 1 (warps 16-31): warps 16-23 build the 8 D tables (barrier-free
//     warp FWHT, one table per warp); warps 24-31 idle pre-barrier. After
//     the barrier all 512 role-1 threads eval out5-7 (1 element each).
// Total LDG/MUFU identical to R9/R11; total FWHT work HALVED (64x8 warps).

__global__ __launch_bounds__(1024) void vqc_fused(const float* __restrict__ inputs,
                                                  const float* __restrict__ weights,
                                                  float* __restrict__ out) {
    __shared__ float sD[8][256];
    __shared__ float s_sz[8][512];
    __shared__ float s_K[3][512];

    const int tid  = threadIdx.x;
    const int lane = tid & 31;
    const int wid  = tid >> 5;
    const int role = tid >> 9;          // warp-uniform (warps 0-15 / 16-31)
    const int eloc = tid & 511;
    const int e    = blockIdx.x * 512 + eloc;

    float sz0, cz0, sz1, cz1, sz2, cz2, sz3, cz3, sz4, cz4, sz5, cz5, sz6, cz6, sz7, cz7;

    if (role == 0) {
        // ---- full-element sincos pipeline ----
        const float4 z0 = *reinterpret_cast<const float4*>(inputs + e * 8);
        const float4 z1 = *reinterpret_cast<const float4*>(inputs + e * 8 + 4);
        __sincosf(z0.x, &sz0, &cz0);  __sincosf(z0.y, &sz1, &cz1);
        __sincosf(z0.z, &sz2, &cz2);  __sincosf(z0.w, &sz3, &cz3);
        __sincosf(z1.x, &sz4, &cz4);  __sincosf(z1.y, &sz5, &cz5);
        __sincosf(z1.z, &sz6, &cz6);  __sincosf(z1.w, &sz7, &cz7);

        s_sz[0][eloc] = sz0; s_sz[1][eloc] = sz1; s_sz[2][eloc] = sz2; s_sz[3][eloc] = sz3;
        s_sz[4][eloc] = sz4; s_sz[5][eloc] = sz5; s_sz[6][eloc] = sz6; s_sz[7][eloc] = sz7;

        // K products for the outputs role 1 evaluates
        float K5 = cz1 * cz3 * cz5;
        float K6 = cz0 * cz2 * cz4 * cz6;
        float K7 = K5 * cz7;
        s_K[0][eloc] = K5; s_K[1][eloc] = K6; s_K[2][eloc] = K7;
    } else if (wid < 24) {
        // ---- FWHT pipeline: warp (wid-16) builds table D_(wid-16) ----
        const int i  = wid - 16;
        const int sh = 6 - 2 * (i >> 1);
        const int A  = (((0xAA >> sh) << sh) >> (i & 1));
        const int msk[16]  = {0x01,0x03,0x06,0x0C,0x18,0x30,0x60,0xC0,
                              0x01,0x02,0x05,0x0A,0x14,0x28,0x50,0xA0};
        const int widx[16] = {7,6,5,4,3,2,1,0, 15,14,13,12,11,10,9,8};
        float th[16];
#pragma unroll
        for (int j = 0; j < 16; j++) th[j] = __ldg(&weights[widx[j]]);

        float C[8];
#pragma unroll
        for (int r = 0; r < 8; r++) {
            const int w = r * 32 + lane;
            float d = 0.0f;
#pragma unroll
            for (int jj = 0; jj < 16; jj++) {
                if (__popc(msk[jj] & A) & 1)                 // warp-uniform
                    d += (__popc(msk[jj] & w) & 1) ? -th[jj] : th[jj];
            }
            C[r] = __cosf(d);
        }
#pragma unroll
        for (int sb = 1; sb < 8; sb <<= 1) {
            float t[8];
#pragma unroll
            for (int r = 0; r < 8; r++)
                t[r] = (r & sb) ? (C[r ^ sb] - C[r]) : (C[r] + C[r ^ sb]);
#pragma unroll
            for (int r = 0; r < 8; r++) C[r] = t[r];
        }
#pragma unroll
        for (int s = 1; s < 32; s <<= 1) {
            float sign = (lane & s) ? -1.0f : 1.0f;
#pragma unroll
            for (int r = 0; r < 8; r++) {
                float o = __shfl_xor_sync(FULL, C[r], s);
                C[r] = fmaf(sign, C[r], o);
            }
        }
#pragma unroll
        for (int r = 0; r < 8; r++)
            sD[i][r * 32 + lane] = C[r] * (1.0f / 256.0f);
    }
    __syncthreads();

    if (role == 0) {
        // ---- eval out0-4 (registers + sD only; identical math to R9/R11) ----
        float o0 = cz0 * fmaf(sD[0][0x60], sz2 * sz1, sD[0][0x00]);

        float o1 = fmaf(sD[1][0xA0], sz2 * sz0, sD[1][0x00]);
        o1 = fmaf(sD[1][0x30], sz3 * sz2, o1);
        o1 = fmaf(sD[1][0x90], sz3 * sz0, o1);
        o1 *= cz1;

        float o2 = fmaf(sD[2][0x50], sz3 * sz1, sD[2][0x00]);
        o2 = fmaf(sD[2][0x18], sz4 * sz3, o2);
        o2 = fmaf(sD[2][0x48], sz4 * sz1, o2);
        o2 *= cz0 * cz2;

        float s0C = sz5 * sz4, s20 = sz2 * sz0;
        float o3 = fmaf(sD[3][0x28], sz4 * sz2, sD[3][0x00]);
        o3 = fmaf(sD[3][0x0C], s0C, o3);
        o3 = fmaf(sD[3][0x24], sz5 * sz2, o3);
        o3 = fmaf(sD[3][0xA0], s20, o3);
        o3 = fmaf(sD[3][0x84], sz5 * sz0, o3);
        o3 = fmaf(sD[3][0xAC], s0C * s20, o3);
        o3 = fmaf(sD[3][0x88], sz4 * sz0, o3);
        o3 *= cz1 * cz3;

        // out4: comp(0xA8); inner sz7,sz6,sz5; outer p4 = {1,sz3,sz1,sz3*sz1}
        float p4[4] = {1.0f, sz3, sz1, sz3 * sz1};
        const int b4[4] = {0, 16, 64, 80};
        float acc4 = 0.0f;
#pragma unroll
        for (int g = 0; g < 4; g++) {
            float4 a = *reinterpret_cast<const float4*>(&sD[4][b4[g]]);
            float4 b = *reinterpret_cast<const float4*>(&sD[4][b4[g] + 4]);
            float lo = fmaf(a.y, sz7, a.x) + sz6 * fmaf(a.w, sz7, a.z);
            float hi = fmaf(b.y, sz7, b.x) + sz6 * fmaf(b.w, sz7, b.z);
            acc4 = fmaf(p4[g], fmaf(sz5, hi, lo), acc4);
        }
        float o4 = (cz0 * cz2 * cz4) * acc4;

        *reinterpret_cast<float4*>(out + e * 8) = make_float4(o0, o1, o2, o3);
        out[e * 8 + 4] = o4;
    } else {
        // ---- eval out5-7 from published sincos (identical math to R9/R11) ----
        const float sz0 = s_sz[0][eloc], sz1 = s_sz[1][eloc];
        const float sz2 = s_sz[2][eloc], sz3 = s_sz[3][eloc];
        const float sz4 = s_sz[4][eloc], sz5 = s_sz[5][eloc];
        const float sz6 = s_sz[6][eloc], sz7 = s_sz[7][eloc];
        const float K5 = s_K[0][eloc], K6 = s_K[1][eloc], K7 = s_K[2][eloc];

        float s42 = sz4 * sz2, s40 = sz4 * sz0, s20 = sz2 * sz0, s420 = s42 * sz0;
        float m53 = sz5 * sz3, m51 = sz5 * sz1, m31 = sz3 * sz1, m531 = m53 * sz1;
        float p8[8] = {1.0f, sz4, sz2, s42, sz0, s40, s20, s420};
        float p6[8] = {1.0f, sz5, sz3, m53, sz1, m51, m31, m531};

        const int b5[8] = {0, 8, 32, 40, 128, 136, 160, 168};
        float acc5 = 0.0f;
#pragma unroll
        for (int g = 0; g < 8; g++) {
            float4 a = *reinterpret_cast<const float4*>(&sD[5][b5[g]]);
            float inner = fmaf(a.y, sz7, a.x) + sz6 * fmaf(a.w, sz7, a.z);
            acc5 = fmaf(p8[g], inner, acc5);
        }
        const int b6[8] = {0, 4, 16, 20, 64, 68, 80, 84};
        float acc6 = 0.0f;
#pragma unroll
        for (int g = 0; g < 8; g++) {
            float2 a = *reinterpret_cast<const float2*>(&sD[6][b6[g]]);
            acc6 = fmaf(p6[g], fmaf(a.y, sz7, a.x), acc6);
        }
        float acc7 = 0.0f;
#pragma unroll
        for (int g = 0; g < 8; g++) {
            float lo = sD[7][b5[g]];
            float hi = sD[7][b5[g] + 2];
            acc7 = fmaf(p8[g], fmaf(hi, sz6, lo), acc7);
        }

        out[e * 8 + 5] = K5 * acc5;
        *reinterpret_cast<float2*>(out + e * 8 + 6) = make_float2(K6 * acc6, K7 * acc7);
    }
}

extern "C" void kernel_launch(void* const* d_in, const int* in_sizes, int n_in,
                              void* d_out, int out_size) {
    const float* inputs  = (const float*)d_in[0];   // (32768, 8) float32
    const float* weights = (const float*)d_in[1];   // (2, 8)     float32
    float* out = (float*)d_out;                     // (32768, 8) float32

    // 64 blocks x 1024 threads: 512 elements/block, warp-specialized roles
    vqc_fused<<<BATCH / 512, 1024>>>(inputs, weights, out);
}

// round 13
// speedup vs baseline: 1.2651x; 1.2651x over previous
#include <cuda_runtime.h>

#define FULL 0xffffffffu
#define BATCH 32768
#define EPB 222            // elements per block; 148 * 222 = 32856 >= 32768

// Fused VQC (math validated R7-R12): out_i = K_i * sum_T D_i[T] * sigma_T.
// R13: R11's warp-specialized structure on a full-chip grid:
//   148 blocks x 512 threads, 222 elements/block (guarded), 1 block/SM.
//   role 0 (warps 0-7): 1 thread = 1 element (threads 222-255 idle); LDG +
//     8 sincos + publish sz[0..7], K5, K6, K7; after barrier eval out0-4.
//   role 1 (warps 8-15): warp w builds D table (w-8) via the validated
//     barrier-free FWHT; after barrier eval out5-7 from published sincos.

__global__ __launch_bounds__(512) void vqc_fused(const float* __restrict__ inputs,
                                                 const float* __restrict__ weights,
                                                 float* __restrict__ out) {
    __shared__ float sD[8][256];
    __shared__ float s_sz[8][EPB];
    __shared__ float s_K[3][EPB];

    const int tid  = threadIdx.x;
    const int lane = tid & 31;
    const int wid  = tid >> 5;
    const int role = tid >> 8;          // warp-uniform
    const int eloc = tid & 255;
    const int e    = blockIdx.x * EPB + eloc;
    const bool act = (eloc < EPB) && (e < BATCH);

    float sz0, cz0, sz1, cz1, sz2, cz2, sz3, cz3, sz4, cz4, sz5, cz5, sz6, cz6, sz7, cz7;

    if (role == 0) {
        if (act) {
            // ---- full-element sincos pipeline ----
            const float4 z0 = *reinterpret_cast<const float4*>(inputs + e * 8);
            const float4 z1 = *reinterpret_cast<const float4*>(inputs + e * 8 + 4);
            __sincosf(z0.x, &sz0, &cz0);  __sincosf(z0.y, &sz1, &cz1);
            __sincosf(z0.z, &sz2, &cz2);  __sincosf(z0.w, &sz3, &cz3);
            __sincosf(z1.x, &sz4, &cz4);  __sincosf(z1.y, &sz5, &cz5);
            __sincosf(z1.z, &sz6, &cz6);  __sincosf(z1.w, &sz7, &cz7);

            s_sz[0][eloc] = sz0; s_sz[1][eloc] = sz1;
            s_sz[2][eloc] = sz2; s_sz[3][eloc] = sz3;
            s_sz[4][eloc] = sz4; s_sz[5][eloc] = sz5;
            s_sz[6][eloc] = sz6; s_sz[7][eloc] = sz7;

            // K products for the outputs role 1 evaluates
            float K5 = cz1 * cz3 * cz5;
            float K6 = cz0 * cz2 * cz4 * cz6;
            float K7 = K5 * cz7;
            s_K[0][eloc] = K5; s_K[1][eloc] = K6; s_K[2][eloc] = K7;
        }
    } else {
        // ---- FWHT pipeline: warp (wid-8) builds table D_(wid-8) ----
        const int i  = wid - 8;
        const int sh = 6 - 2 * (i >> 1);
        const int A  = (((0xAA >> sh) << sh) >> (i & 1));
        const int msk[16]  = {0x01,0x03,0x06,0x0C,0x18,0x30,0x60,0xC0,
                              0x01,0x02,0x05,0x0A,0x14,0x28,0x50,0xA0};
        const int widx[16] = {7,6,5,4,3,2,1,0, 15,14,13,12,11,10,9,8};
        float th[16];
#pragma unroll
        for (int j = 0; j < 16; j++) th[j] = __ldg(&weights[widx[j]]);

        float C[8];
#pragma unroll
        for (int r = 0; r < 8; r++) {
            const int w = r * 32 + lane;
            float d = 0.0f;
#pragma unroll
            for (int jj = 0; jj < 16; jj++) {
                if (__popc(msk[jj] & A) & 1)                 // warp-uniform
                    d += (__popc(msk[jj] & w) & 1) ? -th[jj] : th[jj];
            }
            C[r] = __cosf(d);
        }
#pragma unroll
        for (int sb = 1; sb < 8; sb <<= 1) {
            float t[8];
#pragma unroll
            for (int r = 0; r < 8; r++)
                t[r] = (r & sb) ? (C[r ^ sb] - C[r]) : (C[r] + C[r ^ sb]);
#pragma unroll
            for (int r = 0; r < 8; r++) C[r] = t[r];
        }
#pragma unroll
        for (int s = 1; s < 32; s <<= 1) {
            float sign = (lane & s) ? -1.0f : 1.0f;
#pragma unroll
            for (int r = 0; r < 8; r++) {
                float o = __shfl_xor_sync(FULL, C[r], s);
                C[r] = fmaf(sign, C[r], o);
            }
        }
#pragma unroll
        for (int r = 0; r < 8; r++)
            sD[i][r * 32 + lane] = C[r] * (1.0f / 256.0f);
    }
    __syncthreads();

    if (!act) return;

    if (role == 0) {
        // ---- eval out0-4 (registers + sD only; identical math to R9-R12) ----
        float o0 = cz0 * fmaf(sD[0][0x60], sz2 * sz1, sD[0][0x00]);

        float o1 = fmaf(sD[1][0xA0], sz2 * sz0, sD[1][0x00]);
        o1 = fmaf(sD[1][0x30], sz3 * sz2, o1);
        o1 = fmaf(sD[1][0x90], sz3 * sz0, o1);
        o1 *= cz1;

        float o2 = fmaf(sD[2][0x50], sz3 * sz1, sD[2][0x00]);
        o2 = fmaf(sD[2][0x18], sz4 * sz3, o2);
        o2 = fmaf(sD[2][0x48], sz4 * sz1, o2);
        o2 *= cz0 * cz2;

        float s0C = sz5 * sz4, s20 = sz2 * sz0;
        float o3 = fmaf(sD[3][0x28], sz4 * sz2, sD[3][0x00]);
        o3 = fmaf(sD[3][0x0C], s0C, o3);
        o3 = fmaf(sD[3][0x24], sz5 * sz2, o3);
        o3 = fmaf(sD[3][0xA0], s20, o3);
        o3 = fmaf(sD[3][0x84], sz5 * sz0, o3);
        o3 = fmaf(sD[3][0xAC], s0C * s20, o3);
        o3 = fmaf(sD[3][0x88], sz4 * sz0, o3);
        o3 *= cz1 * cz3;

        // out4: comp(0xA8); inner sz7,sz6,sz5; outer p4 = {1,sz3,sz1,sz3*sz1}
        float p4[4] = {1.0f, sz3, sz1, sz3 * sz1};
        const int b4[4] = {0, 16, 64, 80};
        float acc4 = 0.0f;
#pragma unroll
        for (int g = 0; g < 4; g++) {
            float4 a = *reinterpret_cast<const float4*>(&sD[4][b4[g]]);
            float4 b = *reinterpret_cast<const float4*>(&sD[4][b4[g] + 4]);
            float lo = fmaf(a.y, sz7, a.x) + sz6 * fmaf(a.w, sz7, a.z);
            float hi = fmaf(b.y, sz7, b.x) + sz6 * fmaf(b.w, sz7, b.z);
            acc4 = fmaf(p4[g], fmaf(sz5, hi, lo), acc4);
        }
        float o4 = (cz0 * cz2 * cz4) * acc4;

        *reinterpret_cast<float4*>(out + e * 8) = make_float4(o0, o1, o2, o3);
        out[e * 8 + 4] = o4;
    } else {
        // ---- eval out5-7 from published sincos (identical math to R9-R12) ----
        const float sz0 = s_sz[0][eloc], sz1 = s_sz[1][eloc];
        const float sz2 = s_sz[2][eloc], sz3 = s_sz[3][eloc];
        const float sz4 = s_sz[4][eloc], sz5 = s_sz[5][eloc];
        const float sz6 = s_sz[6][eloc], sz7 = s_sz[7][eloc];
        const float K5 = s_K[0][eloc], K6 = s_K[1][eloc], K7 = s_K[2][eloc];

        float s42 = sz4 * sz2, s40 = sz4 * sz0, s20 = sz2 * sz0, s420 = s42 * sz0;
        float m53 = sz5 * sz3, m51 = sz5 * sz1, m31 = sz3 * sz1, m531 = m53 * sz1;
        float p8[8] = {1.0f, sz4, sz2, s42, sz0, s40, s20, s420};
        float p6[8] = {1.0f, sz5, sz3, m53, sz1, m51, m31, m531};

        const int b5[8] = {0, 8, 32, 40, 128, 136, 160, 168};
        float acc5 = 0.0f;
#pragma unroll
        for (int g = 0; g < 8; g++) {
            float4 a = *reinterpret_cast<const float4*>(&sD[5][b5[g]]);
            float inner = fmaf(a.y, sz7, a.x) + sz6 * fmaf(a.w, sz7, a.z);
            acc5 = fmaf(p8[g], inner, acc5);
        }
        const int b6[8] = {0, 4, 16, 20, 64, 68, 80, 84};
        float acc6 = 0.0f;
#pragma unroll
        for (int g = 0; g < 8; g++) {
            float2 a = *reinterpret_cast<const float2*>(&sD[6][b6[g]]);
            acc6 = fmaf(p6[g], fmaf(a.y, sz7, a.x), acc6);
        }
        float acc7 = 0.0f;
#pragma unroll
        for (int g = 0; g < 8; g++) {
            float lo = sD[7][b5[g]];
            float hi = sD[7][b5[g] + 2];
            acc7 = fmaf(p8[g], fmaf(hi, sz6, lo), acc7);
        }

        out[e * 8 + 5] = K5 * acc5;
        *reinterpret_cast<float2*>(out + e * 8 + 6) = make_float2(K6 * acc6, K7 * acc7);
    }
}

extern "C" void kernel_launch(void* const* d_in, const int* in_sizes, int n_in,
                              void* d_out, int out_size) {
    const float* inputs  = (const float*)d_in[0];   // (32768, 8) float32
    const float* weights = (const float*)d_in[1];   // (2, 8)     float32
    float* out = (float*)d_out;                     // (32768, 8) float32

    // 148 blocks x 512 threads: 222 elements/block (guarded), 1 block/SM,
    // warps 0-7 sincos+eval0-4, warps 8-15 FWHT+eval5-7
    const int n_blocks = (BATCH + EPB - 1) / EPB;   // 148
    vqc_fused<<<n_blocks, 512>>>(inputs, weights, out);
}